// round 5
// baseline (speedup 1.0000x reference)
#include <cuda_runtime.h>
#include <math.h>

#define BSZ 4096
#define HD  128
#define TDIM 768
#define PCAP (1 << 20)

// ---------------- device scratch ----------------
__device__ float g_LN[BSZ * HD];        // normalized logits  [B][128]
__device__ float g_Tn[BSZ];             // teacher row inv-norms
__device__ float g_Ht[HD * BSZ];        // hash^T   [128][4096]
__device__ float g_Tt[TDIM * BSZ];      // normalized teacher^T [768][4096]
__device__ float g_GH[HD * HD];         // H^T H
__device__ float g_C [HD * TDIM];       // H^T T
__device__ float g_TT[TDIM * TDIM];     // T^T T
__device__ float g_denom[BSZ];
__device__ float g_pos[BSZ];
__device__ float g_cnt[BSZ];
__device__ float g_quant;
__device__ float g_ST;
__device__ int2  g_plist[PCAP];
__device__ int   g_pcount;

__device__ __forceinline__ void mma_tf32(float* d, const unsigned* a, const unsigned* b) {
    asm volatile(
        "mma.sync.aligned.m16n8k8.row.col.f32.tf32.tf32.f32 "
        "{%0,%1,%2,%3}, {%4,%5,%6,%7}, {%8,%9}, {%0,%1,%2,%3};"
        : "+f"(d[0]), "+f"(d[1]), "+f"(d[2]), "+f"(d[3])
        : "r"(a[0]), "r"(a[1]), "r"(a[2]), "r"(a[3]), "r"(b[0]), "r"(b[1]));
}

// ---------------- zero accumulators ----------------
__global__ void k_zero() {
    int i = blockIdx.x * 256 + threadIdx.x;
    int n = gridDim.x * 256;
    for (int j = i; j < TDIM * TDIM; j += n) g_TT[j] = 0.f;
    for (int j = i; j < HD * TDIM;  j += n) g_C[j]  = 0.f;
    if (i < HD * HD) g_GH[i] = 0.f;
    if (i < BSZ) { g_denom[i] = 0.f; g_pos[i] = 0.f; g_cnt[i] = 0.f; }
    if (i == 0) { g_quant = 0.f; g_ST = 0.f; g_pcount = 0; }
}

// ---------------- normalize logits + quant partial ----------------
__global__ void k_norm_logits(const float* __restrict__ x) {
    int row = blockIdx.x;
    int t = threadIdx.x;                 // 128 threads
    float v = x[row * HD + t];
    float ss = v * v;
    float q = fabsf(fabsf(v) - 1.0f);
    #pragma unroll
    for (int o = 16; o >= 1; o >>= 1) {
        ss += __shfl_xor_sync(0xffffffffu, ss, o);
        q  += __shfl_xor_sync(0xffffffffu, q, o);
    }
    __shared__ float sred[4], qred[4];
    __shared__ float sinv;
    int w = t >> 5, l = t & 31;
    if (l == 0) { sred[w] = ss; qred[w] = q; }
    __syncthreads();
    if (t == 0) {
        float tot = sred[0] + sred[1] + sred[2] + sred[3];
        float qt  = qred[0] + qred[1] + qred[2] + qred[3];
        atomicAdd(&g_quant, qt);
        sinv = 1.0f / fmaxf(sqrtf(tot), 1e-12f);
    }
    __syncthreads();
    g_LN[row * HD + t] = v * sinv;
}

// ---------------- teacher row inv norms ----------------
__global__ void k_tnorm(const float* __restrict__ x) {
    int row = blockIdx.x;
    int t = threadIdx.x;                 // 256 threads
    float v0 = x[row * TDIM + t];
    float v1 = x[row * TDIM + 256 + t];
    float v2 = x[row * TDIM + 512 + t];
    float ss = v0 * v0 + v1 * v1 + v2 * v2;
    #pragma unroll
    for (int o = 16; o >= 1; o >>= 1) ss += __shfl_xor_sync(0xffffffffu, ss, o);
    __shared__ float sred[8];
    if ((t & 31) == 0) sred[t >> 5] = ss;
    __syncthreads();
    if (t == 0) {
        float tot = 0.f;
        #pragma unroll
        for (int i = 0; i < 8; i++) tot += sred[i];
        g_Tn[row] = 1.0f / fmaxf(sqrtf(tot), 1e-12f);
    }
}

// ---------------- tiled transpose (optional row scaling) ----------------
__global__ void k_transpose(const float* __restrict__ src, float* __restrict__ dst,
                            int R, int C, int scaled) {
    __shared__ float t[32][33];
    int c0 = blockIdx.x * 32, r0 = blockIdx.y * 32;
    int x = threadIdx.x, y = threadIdx.y;   // block (32, 8)
    #pragma unroll
    for (int i = 0; i < 32; i += 8) {
        float v = src[(r0 + y + i) * C + c0 + x];
        if (scaled) v *= g_Tn[r0 + y + i];
        t[y + i][x] = v;
    }
    __syncthreads();
    #pragma unroll
    for (int i = 0; i < 32; i += 8) dst[(c0 + y + i) * R + r0 + x] = t[x][y + i];
}

// ---------------- mask scan -> positive pair list ----------------
__global__ void k_mask(const int* __restrict__ pmask) {
    const int4* m4 = (const int4*)pmask;
    int total4 = (BSZ * BSZ) >> 2;
    int stride = gridDim.x * blockDim.x;
    for (int i = blockIdx.x * blockDim.x + threadIdx.x; i < total4; i += stride) {
        int4 v = m4[i];
        int base = i << 2;
        if (v.x | v.y | v.z | v.w) {
            #pragma unroll
            for (int k = 0; k < 4; k++) {
                int e = (k == 0) ? v.x : (k == 1) ? v.y : (k == 2) ? v.z : v.w;
                if (e != 0) {
                    int idx = base + k;
                    int slot = atomicAdd(&g_pcount, 1);
                    if (slot < PCAP) g_plist[slot] = make_int2(idx >> 12, idx & 4095);
                }
            }
        }
    }
}

// ---------------- positive pair dots (exact fp32) ----------------
__global__ void k_pos() {
    int lane = threadIdx.x & 31;
    int wid = (blockIdx.x * blockDim.x + threadIdx.x) >> 5;
    int nw = (gridDim.x * blockDim.x) >> 5;
    int count = g_pcount;
    if (count > PCAP) count = PCAP;
    const float4* LN4 = (const float4*)g_LN;   // row stride 32 float4
    for (int p = wid; p < count; p += nw) {
        int2 pr = g_plist[p];
        float4 a = LN4[pr.x * 32 + lane];
        float4 b = LN4[pr.y * 32 + lane];
        float d = a.x * b.x + a.y * b.y + a.z * b.z + a.w * b.w;
        #pragma unroll
        for (int o = 16; o >= 1; o >>= 1) d += __shfl_xor_sync(0xffffffffu, d, o);
        if (lane == 0) {
            atomicAdd(&g_pos[pr.x], d * 5.0f);
            atomicAdd(&g_cnt[pr.x], 1.0f);
        }
    }
}

// ======== 128x128 mma tile core ========
// smem: unsigned [128][36]; bank = (4r + c) & 31 -> conflict-free frag reads
// 8 warps = 2(wm) x 4(wn); warp tile 64x32; frags 4(mi) x 4(ni)

#define LOAD_TILES(A4src, B4src)                                            \
    do {                                                                    \
        _Pragma("unroll")                                                   \
        for (int s = 0; s < 4; s++) {                                       \
            int idx = tid + s * 256;                                        \
            int r = idx >> 3, c8 = idx & 7;                                 \
            *(float4*)&As[r][c8 * 4] = (A4src);                             \
            *(float4*)&Bs[r][c8 * 4] = (B4src);                             \
        }                                                                   \
    } while (0)

#define MMA_CHUNK()                                                         \
    do {                                                                    \
        _Pragma("unroll")                                                   \
        for (int kk = 0; kk < 4; kk++) {                                    \
            int kb = kk * 8;                                                \
            unsigned af[4][4], bf[4][2];                                    \
            _Pragma("unroll")                                               \
            for (int mi = 0; mi < 4; mi++) {                                \
                int rr = wm * 64 + mi * 16 + fr;                            \
                af[mi][0] = As[rr][kb + fc];                                \
                af[mi][1] = As[rr + 8][kb + fc];                            \
                af[mi][2] = As[rr][kb + fc + 4];                            \
                af[mi][3] = As[rr + 8][kb + fc + 4];                        \
            }                                                               \
            _Pragma("unroll")                                               \
            for (int ni = 0; ni < 4; ni++) {                                \
                int rn = wn * 32 + ni * 8 + fr;                             \
                bf[ni][0] = Bs[rn][kb + fc];                                \
                bf[ni][1] = Bs[rn][kb + fc + 4];                            \
            }                                                               \
            _Pragma("unroll")                                               \
            for (int mi = 0; mi < 4; mi++)                                  \
                _Pragma("unroll")                                           \
                for (int ni = 0; ni < 4; ni++)                              \
                    mma_tf32(acc[mi][ni], af[mi], bf[ni]);                  \
        }                                                                   \
    } while (0)

// ---------------- generic A*B^T GEMM (k-contig operands), split-K ----------
__global__ void __launch_bounds__(256) k_mma(const float* __restrict__ A,
                                             const float* __restrict__ Bm,
                                             float* __restrict__ out, int ldo,
                                             int kPer) {
    __shared__ __align__(16) unsigned As[128][36];
    __shared__ __align__(16) unsigned Bs[128][36];
    int m0 = blockIdx.x * 128, n0 = blockIdx.y * 128;
    int kBeg = blockIdx.z * kPer;
    int tid = threadIdx.x, lane = tid & 31, w = tid >> 5;
    int wm = w & 1, wn = w >> 1;
    int fr = lane >> 2, fc = lane & 3;
    const float4* A4 = (const float4*)A;    // row stride 1024 float4
    const float4* B4 = (const float4*)Bm;
    float acc[4][4][4] = {};
    for (int k0 = kBeg; k0 < kBeg + kPer; k0 += 32) {
        __syncthreads();
        LOAD_TILES(A4[(m0 + r) * 1024 + (k0 >> 2) + c8],
                   B4[(n0 + r) * 1024 + (k0 >> 2) + c8]);
        __syncthreads();
        MMA_CHUNK();
    }
    #pragma unroll
    for (int mi = 0; mi < 4; mi++)
        #pragma unroll
        for (int ni = 0; ni < 4; ni++)
            #pragma unroll
            for (int h = 0; h < 2; h++)
                #pragma unroll
                for (int q = 0; q < 2; q++) {
                    int gi = m0 + wm * 64 + mi * 16 + fr + h * 8;
                    int gj = n0 + wn * 32 + ni * 8 + fc * 2 + q;
                    atomicAdd(&out[gi * ldo + gj], acc[mi][ni][h * 2 + q]);
                }
}

// ---------------- T^T T upper-triangle 128-tiles ----------------
__global__ void __launch_bounds__(256) k_mma_tri(int kPer) {
    __shared__ __align__(16) unsigned As[128][36];
    __shared__ __align__(16) unsigned Bs[128][36];
    int t = blockIdx.x, tm = 0;                 // 6x6 tiles, upper = 21
    while (t >= 6 - tm) { t -= 6 - tm; tm++; }
    int m0 = tm * 128, n0 = (tm + t) * 128;
    int kBeg = blockIdx.z * kPer;
    int tid = threadIdx.x, lane = tid & 31, w = tid >> 5;
    int wm = w & 1, wn = w >> 1;
    int fr = lane >> 2, fc = lane & 3;
    const float4* A4 = (const float4*)g_Tt;
    float acc[4][4][4] = {};
    for (int k0 = kBeg; k0 < kBeg + kPer; k0 += 32) {
        __syncthreads();
        LOAD_TILES(A4[(m0 + r) * 1024 + (k0 >> 2) + c8],
                   A4[(n0 + r) * 1024 + (k0 >> 2) + c8]);
        __syncthreads();
        MMA_CHUNK();
    }
    #pragma unroll
    for (int mi = 0; mi < 4; mi++)
        #pragma unroll
        for (int ni = 0; ni < 4; ni++)
            #pragma unroll
            for (int h = 0; h < 2; h++)
                #pragma unroll
                for (int q = 0; q < 2; q++) {
                    int gi = m0 + wm * 64 + mi * 16 + fr + h * 8;
                    int gj = n0 + wn * 32 + ni * 8 + fc * 2 + q;
                    atomicAdd(&g_TT[gi * TDIM + gj], acc[mi][ni][h * 2 + q]);
                }
}

// ---------------- distill square-reduce ----------------
__global__ void k_sq3() {
    int i = blockIdx.x * 256 + threadIdx.x;
    int n = gridDim.x * 256;
    float s = 0.f;
    for (int j = i; j < HD * HD; j += n) {
        float v = g_GH[j]; s += v * v * (1.f / (128.f * 128.f));
    }
    for (int j = i; j < HD * TDIM; j += n) {
        float v = g_C[j]; s -= 2.f * v * v * (1.f / 128.f);
    }
    for (int j = i; j < TDIM * TDIM; j += n) {
        int r = j / TDIM, c = j % TDIM;
        if (c < r) continue;
        float v = g_TT[j];
        s += (c == r) ? v * v : 2.f * v * v;
    }
    #pragma unroll
    for (int o = 16; o >= 1; o >>= 1) s += __shfl_xor_sync(0xffffffffu, s, o);
    __shared__ float red[8];
    if ((threadIdx.x & 31) == 0) red[threadIdx.x >> 5] = s;
    __syncthreads();
    if (threadIdx.x == 0) {
        float tot = 0.f;
        #pragma unroll
        for (int k = 0; k < 8; k++) tot += red[k];
        atomicAdd(&g_ST, tot / ((float)BSZ * (float)BSZ));
    }
}

// ---------------- contrastive: symmetric upper-tri 128-tiles, denom only ----
__global__ void __launch_bounds__(256) k_cont() {
    __shared__ __align__(16) unsigned As[128][36];
    __shared__ __align__(16) unsigned Bs[128][36];
    __shared__ float sRd[128], sCd[128];
    int t = blockIdx.x, tm = 0;                 // 32x32 tiles, upper = 528
    while (t >= 32 - tm) { t -= 32 - tm; tm++; }
    int i0 = tm * 128, j0 = (tm + t) * 128;
    bool diag = (i0 == j0);
    int tid = threadIdx.x, lane = tid & 31, w = tid >> 5;
    int wm = w & 1, wn = w >> 1;
    int fr = lane >> 2, fc = lane & 3;
    if (tid < 128) { sRd[tid] = 0.f; sCd[tid] = 0.f; }
    const float4* LN4 = (const float4*)g_LN;   // row stride = 32 float4
    float acc[4][4][4] = {};
    #pragma unroll
    for (int kc = 0; kc < 4; kc++) {
        __syncthreads();
        LOAD_TILES(LN4[(i0 + r) * 32 + kc * 8 + c8],
                   LN4[(j0 + r) * 32 + kc * 8 + c8]);
        __syncthreads();
        MMA_CHUNK();
    }

    // ---- epilogue: exp sums, both orientations ----
    float dR[4][2] = {}, dC[4][2] = {};
    #pragma unroll
    for (int mi = 0; mi < 4; mi++)
        #pragma unroll
        for (int ni = 0; ni < 4; ni++)
            #pragma unroll
            for (int h = 0; h < 2; h++)
                #pragma unroll
                for (int q = 0; q < 2; q++) {
                    int gi = i0 + wm * 64 + mi * 16 + fr + h * 8;
                    int gj = j0 + wn * 32 + ni * 8 + fc * 2 + q;
                    float e = __expf(acc[mi][ni][h * 2 + q] * 5.0f);
                    if (gj != gi) dR[mi][h] += e;
                    if (!diag) dC[ni][q] += e;
                }
    // row reduce over fc lanes (width 4)
    #pragma unroll
    for (int mi = 0; mi < 4; mi++)
        #pragma unroll
        for (int h = 0; h < 2; h++) {
            #pragma unroll
            for (int o = 2; o >= 1; o >>= 1)
                dR[mi][h] += __shfl_down_sync(0xffffffffu, dR[mi][h], o, 4);
            if (fc == 0)
                atomicAdd(&sRd[wm * 64 + mi * 16 + fr + h * 8], dR[mi][h]);
        }
    // col reduce over fr lanes (xor 4,8,16)
    if (!diag) {
        #pragma unroll
        for (int ni = 0; ni < 4; ni++)
            #pragma unroll
            for (int q = 0; q < 2; q++) {
                #pragma unroll
                for (int o = 16; o >= 4; o >>= 1)
                    dC[ni][q] += __shfl_xor_sync(0xffffffffu, dC[ni][q], o);
                if (fr == 0)
                    atomicAdd(&sCd[wn * 32 + ni * 8 + fc * 2 + q], dC[ni][q]);
            }
    }
    __syncthreads();
    if (tid < 128) {
        atomicAdd(&g_denom[i0 + tid], sRd[tid]);
        if (!diag) atomicAdd(&g_denom[j0 + tid], sCd[tid]);
    }
}

// ---------------- final combine ----------------
__global__ void k_combine(float* __restrict__ out) {
    int tid = threadIdx.x;               // 256 threads
    float cont = 0.f;
    for (int i = tid; i < BSZ; i += 256)
        cont += logf(g_denom[i]) - g_pos[i] / fmaxf(g_cnt[i], 1.0f);
    #pragma unroll
    for (int o = 16; o >= 1; o >>= 1)
        cont += __shfl_xor_sync(0xffffffffu, cont, o);
    __shared__ float r0[8];
    if ((tid & 31) == 0) r0[tid >> 5] = cont;
    __syncthreads();
    if (tid == 0) {
        float cT = 0.f;
        #pragma unroll
        for (int i = 0; i < 8; i++) cT += r0[i];
        float quant = g_quant / ((float)BSZ * (float)HD);
        out[0] = cT / (float)BSZ + 0.5f * g_ST + 0.01f * quant;
    }
}

// ---------------- launch ----------------
extern "C" void kernel_launch(void* const* d_in, const int* in_sizes, int n_in,
                              void* d_out, int out_size) {
    const float* logits = (const float*)d_in[0];
    const float* hash   = (const float*)d_in[1];
    const float* teach  = (const float*)d_in[2];
    const int*   pmask  = (const int*)d_in[3];
    float* out = (float*)d_out;

    float* p_Ht; cudaGetSymbolAddress((void**)&p_Ht, g_Ht);
    float* p_Tt; cudaGetSymbolAddress((void**)&p_Tt, g_Tt);
    float* p_GH; cudaGetSymbolAddress((void**)&p_GH, g_GH);
    float* p_C;  cudaGetSymbolAddress((void**)&p_C,  g_C);

    k_zero<<<512, 256>>>();
    k_norm_logits<<<BSZ, 128>>>(logits);
    k_tnorm<<<BSZ, 256>>>(teach);
    k_transpose<<<dim3(HD / 32, BSZ / 32), dim3(32, 8)>>>(hash, p_Ht, BSZ, HD, 0);
    k_transpose<<<dim3(TDIM / 32, BSZ / 32), dim3(32, 8)>>>(teach, p_Tt, BSZ, TDIM, 1);
    k_mask<<<2048, 256>>>(pmask);
    k_pos<<<512, 256>>>();
    // G_H = H^T H : one 128-tile, split-K 32
    k_mma<<<dim3(1, 1, 32), 256>>>(p_Ht, p_Ht, p_GH, HD, 128);
    // C = H^T T : 1x6 tiles, split-K 16
    k_mma<<<dim3(1, 6, 16), 256>>>(p_Ht, p_Tt, p_C, TDIM, 256);
    // T^T T upper triangle : 21 tiles, split-K 16
    k_mma_tri<<<dim3(21, 1, 16), 256>>>(256);
    k_sq3<<<512, 256>>>();
    // contrastive: 528 upper-triangle 128-tiles
    k_cont<<<528, 256>>>();
    k_combine<<<1, 256>>>(out);
}